// round 1
// baseline (speedup 1.0000x reference)
#include <cuda_runtime.h>
#include <cuda_bf16.h>

#define NBINS 36
#define PS 32
#define BLK 128           // threads per block, one patch per block
#define TWO_PI_F 6.2831855f   // 0x40C90FDB, f32(2*pi)
#define PI_F     3.1415927f   // 0x40490FDB, f32(pi)

__global__ __launch_bounds__(BLK)
void OrientationFinder_83193516523885_kernel(
    const float* __restrict__ x,
    const float* __restrict__ gxw,
    const float* __restrict__ gyw,
    const float* __restrict__ smw,
    const float* __restrict__ gk,
    float* __restrict__ out)
{
    __shared__ float tile[PS][PS + 1];      // +1 pad -> conflict-free strip reads
    __shared__ float hist[NBINS][BLK];      // per-thread private columns (bank = lane)
    __shared__ float binsum[NBINS];

    const int t = threadIdx.x;
    const long long base = (long long)blockIdx.x * (PS * PS);

    // ---- load patch (2x float4 per thread, coalesced) ----
    const float4* xv = (const float4*)(x + base);
    #pragma unroll
    for (int k = 0; k < 2; ++k) {
        int i4 = t + k * BLK;               // 0..255
        float4 v = xv[i4];
        int row = i4 >> 3;                  // 8 float4 per row
        int col = (i4 & 7) << 2;
        tile[row][col + 0] = v.x;
        tile[row][col + 1] = v.y;
        tile[row][col + 2] = v.z;
        tile[row][col + 3] = v.w;
    }
    // ---- zero private histogram column ----
    #pragma unroll
    for (int b = 0; b < NBINS; ++b) hist[b][t] = 0.0f;

    const float w0x = gxw[0], w1x = gxw[1], w2x = gxw[2];
    const float w0y = gyw[0], w1y = gyw[1], w2y = gyw[2];

    __syncthreads();

    // ---- main loop: thread handles 8 consecutive pixels of one row ----
    const int r  = t >> 2;                  // 0..31
    const int c0 = (t & 3) << 3;            // 0,8,16,24
    const int rm = (r > 0) ? r - 1 : 0;
    const int rp = (r < PS - 1) ? r + 1 : PS - 1;

    float up[8], dn[8], cl[10], gkr[8];
    #pragma unroll
    for (int i = 0; i < 8; ++i) {
        up[i] = tile[rm][c0 + i];
        dn[i] = tile[rp][c0 + i];
        cl[i + 1] = tile[r][c0 + i];
    }
    cl[0] = tile[r][(c0 > 0) ? c0 - 1 : 0];
    cl[9] = tile[r][(c0 + 8 < PS) ? c0 + 8 : PS - 1];

    {   // gk row strip: two float4 loads (L1-resident across all blocks)
        const float4* g4 = (const float4*)(gk + r * PS + c0);
        float4 a = g4[0], b = g4[1];
        gkr[0] = a.x; gkr[1] = a.y; gkr[2] = a.z; gkr[3] = a.w;
        gkr[4] = b.x; gkr[5] = b.y; gkr[6] = b.z; gkr[7] = b.w;
    }

    #pragma unroll
    for (int i = 0; i < 8; ++i) {
        const float a = cl[i], bmid = cl[i + 1], c = cl[i + 2];
        // exact reference association: (w0*a + w1*b) + w2*c, no fma contraction
        float gx = __fadd_rn(__fadd_rn(__fmul_rn(w0x, a),
                                       __fmul_rn(w1x, bmid)),
                             __fmul_rn(w2x, c));
        float gy = __fadd_rn(__fadd_rn(__fmul_rn(w0y, up[i]),
                                       __fmul_rn(w1y, bmid)),
                             __fmul_rn(w2y, dn[i]));
        float s = __fadd_rn(__fadd_rn(__fmul_rn(gx, gx), __fmul_rn(gy, gy)),
                            1e-10f);
        float m = __fmul_rn(__fsqrt_rn(s), gkr[i]);
        if (m > 0.001f) {                   // keep mask; zero-weight pixels skipped
            float ori = atan2f(gy, gx);     // libdevice-identical to XLA lowering
            float o = ori;
            if (o < 0.0f) o = __fadd_rn(o, TWO_PI_F);   // jnp.mod(ori, 2pi), -0.0 kept
            float ob  = __fdiv_rn(__fmul_rn(36.0f, o), TWO_PI_F);
            float bf  = floorf(ob);
            float wo1 = __fsub_rn(ob, bf);
            int   b   = (int)bf;
            if (b > NBINS - 1) b -= NBINS;  // o_big == 36.0 edge -> bin 0 (mod 36)
            float w = __fmul_rn(__fsub_rn(1.0f, wo1), m);
            hist[b][t] = __fadd_rn(hist[b][t], w);   // private column, no atomic
        }
    }

    __syncthreads();

    // ---- reduce 128 columns per bin: warp w handles bins [9w, 9w+9) ----
    const int wid  = t >> 5;
    const int lane = t & 31;
    #pragma unroll
    for (int k = 0; k < 9; ++k) {
        int b = wid * 9 + k;
        float v = hist[b][lane] + hist[b][lane + 32]
                + hist[b][lane + 64] + hist[b][lane + 96];
        #pragma unroll
        for (int off = 16; off > 0; off >>= 1)
            v += __shfl_xor_sync(0xffffffffu, v, off);
        if (lane == 0) binsum[b] = v * 0.0009765625f;   // /1024 exact (power of 2)
    }
    __syncthreads();

    // ---- smoothing + first-index argmax (warp 0) ----
    if (t < 32) {
        const float s0 = smw[0], s1 = smw[1], s2 = smw[2];
        // lane l: bin l ; lanes 0..3 additionally bins 32..35
        float hm = (lane > 0) ? binsum[lane - 1] : 0.0f;
        float hc = binsum[lane];
        float hp = binsum[lane + 1];        // lane 31 -> binsum[32], valid (<36)
        float v1 = __fadd_rn(__fadd_rn(__fmul_rn(s0, hm), __fmul_rn(s1, hc)),
                             __fmul_rn(s2, hp));
        int i1 = lane;
        if (lane < 4) {
            int b2 = 32 + lane;
            float hm2 = binsum[b2 - 1];
            float hc2 = binsum[b2];
            float hp2 = (b2 < NBINS - 1) ? binsum[b2 + 1] : 0.0f;
            float v2 = __fadd_rn(__fadd_rn(__fmul_rn(s0, hm2), __fmul_rn(s1, hc2)),
                                 __fmul_rn(s2, hp2));
            if (v2 > v1) { v1 = v2; i1 = b2; }   // tie keeps smaller index
        }
        #pragma unroll
        for (int off = 16; off > 0; off >>= 1) {
            float ov = __shfl_xor_sync(0xffffffffu, v1, off);
            int   oi = __shfl_xor_sync(0xffffffffu, i1, off);
            if (ov > v1 || (ov == v1 && oi < i1)) { v1 = ov; i1 = oi; }
        }
        if (lane == 0) {
            float fi = (float)i1;
            float tt = __fdiv_rn(__fmul_rn(TWO_PI_F, fi), 36.0f);
            out[blockIdx.x] = -__fsub_rn(tt, PI_F);   // -(2pi*idx/36 - pi)
        }
    }
}

extern "C" void kernel_launch(void* const* d_in, const int* in_sizes, int n_in,
                              void* d_out, int out_size)
{
    const float* x   = (const float*)d_in[0];
    const float* gxw = (const float*)d_in[1];
    const float* gyw = (const float*)d_in[2];
    const float* smw = (const float*)d_in[3];
    const float* gk  = (const float*)d_in[4];
    float* out = (float*)d_out;

    int B = in_sizes[0] / (PS * PS);
    OrientationFinder_83193516523885_kernel<<<B, BLK>>>(x, gxw, gyw, smw, gk, out);
}

// round 2
// speedup vs baseline: 1.0891x; 1.0891x over previous
#include <cuda_runtime.h>
#include <cuda_bf16.h>

#define NBINS 36
#define PS 32
#define BLK 128
#define HSTRIDE 132              // hist row stride: RMW bank=t, LDS.128 reads conflict-free
#define TWO_PI_F 6.2831855f      // f32(2*pi)
#define PI_F     3.1415927f      // f32(pi)

typedef unsigned long long ull;

__device__ __forceinline__ ull f2_add(ull a, ull b) {
    ull r; asm("add.rn.f32x2 %0,%1,%2;" : "=l"(r) : "l"(a), "l"(b)); return r;
}
__device__ __forceinline__ ull f2_mul(ull a, ull b) {
    ull r; asm("mul.rn.f32x2 %0,%1,%2;" : "=l"(r) : "l"(a), "l"(b)); return r;
}
__device__ __forceinline__ ull packf2(float a, float b) {
    ull r; asm("mov.b64 %0,{%1,%2};" : "=l"(r) : "f"(a), "f"(b)); return r;
}
__device__ __forceinline__ void unpackf2(ull v, float& a, float& b) {
    asm("mov.b64 {%0,%1},%2;" : "=f"(a), "=f"(b) : "l"(v));
}
__device__ __forceinline__ float rsq_approx(float x) {
    float r; asm("rsqrt.approx.f32 %0,%1;" : "=f"(r) : "f"(x)); return r;
}

__global__ __launch_bounds__(BLK, 8)
void OrientationFinder_83193516523885_kernel(
    const float* __restrict__ x,
    const float* __restrict__ gxw,
    const float* __restrict__ gyw,
    const float* __restrict__ smw,
    const float* __restrict__ gk,
    float* __restrict__ out)
{
    __shared__ __align__(16) float tile[PS][36];          // stride 36: float4-aligned rows
    __shared__ __align__(16) float hist[NBINS * HSTRIDE]; // [bin][thread], padded
    __shared__ float part[144];                           // [quarter][bin] partials
    __shared__ float binsum[40];

    const int t = threadIdx.x;
    const long long base = (long long)blockIdx.x * (PS * PS);

    const int r  = t >> 2;            // row 0..31
    const int c0 = (t & 3) << 3;      // col 0,8,16,24
    const int rm = (r > 0) ? r - 1 : 0;
    const int rp = (r < PS - 1) ? r + 1 : PS - 1;

    // ---- load own strip (coalesced: lane l covers bytes [32l, 32l+32)) ----
    const float4* xv = (const float4*)(x + base);
    float4 v0 = xv[2 * t];
    float4 v1 = xv[2 * t + 1];
    float s0 = v0.x, s1 = v0.y, s2 = v0.z, s3 = v0.w;
    float s4 = v1.x, s5 = v1.y, s6 = v1.z, s7 = v1.w;

    // store strip to tile (2 STS.128, conflict-free)
    *(float4*)&tile[r][c0]     = v0;
    *(float4*)&tile[r][c0 + 4] = v1;

    // ---- flat float4 zeroing of hist: 36*132 = 4752 floats = 1188 float4 ----
    {
        float4 z4 = make_float4(0.f, 0.f, 0.f, 0.f);
        float4* hz = (float4*)hist;
        #pragma unroll
        for (int i = 0; i < 9; ++i) hz[t + i * BLK] = z4;
        if (t < 1188 - 9 * BLK) hz[t + 9 * BLK] = z4;
    }

    const ull W0X = packf2(gxw[0], gxw[0]);
    const ull W1X = packf2(gxw[1], gxw[1]);
    const ull W2X = packf2(gxw[2], gxw[2]);
    const ull W0Y = packf2(gyw[0], gyw[0]);
    const ull W1Y = packf2(gyw[1], gyw[1]);
    const ull W2Y = packf2(gyw[2], gyw[2]);
    const ull EPS = packf2(1e-10f, 1e-10f);

    float gkr[8];
    {   // gk strip (L1-resident)
        float4 a = *(const float4*)(gk + r * PS + c0);
        float4 b = *(const float4*)(gk + r * PS + c0 + 4);
        gkr[0] = a.x; gkr[1] = a.y; gkr[2] = a.z; gkr[3] = a.w;
        gkr[4] = b.x; gkr[5] = b.y; gkr[6] = b.z; gkr[7] = b.w;
    }

    __syncthreads();

    const float left  = (c0 > 0)       ? tile[r][c0 - 1] : s0;   // edge replicate
    const float right = (c0 + 8 < PS)  ? tile[r][c0 + 8] : s7;

    float* hcol = hist + t;

    // ---- main loop: 4 pixel-pairs, packed f32x2 gradient/magnitude ----
    float sa[10];
    sa[0] = left; sa[1] = s0; sa[2] = s1; sa[3] = s2; sa[4] = s3;
    sa[5] = s4; sa[6] = s5; sa[7] = s6; sa[8] = s7; sa[9] = right;

    #pragma unroll
    for (int k = 0; k < 4; ++k) {
        const int i = 2 * k;
        ull A  = packf2(sa[i],     sa[i + 1]);   // left neighbors
        ull Bc = packf2(sa[i + 1], sa[i + 2]);   // centers
        ull C  = packf2(sa[i + 2], sa[i + 3]);   // right neighbors
        ull U  = *(const ull*)&tile[rm][c0 + i]; // up pair   (LDS.64, 8B aligned)
        ull D  = *(const ull*)&tile[rp][c0 + i]; // down pair

        // exact reference association: (w0*a + w1*b) + w2*c, rn per lane
        ull gx2 = f2_add(f2_add(f2_mul(W0X, A), f2_mul(W1X, Bc)), f2_mul(W2X, C));
        ull gy2 = f2_add(f2_add(f2_mul(W0Y, U), f2_mul(W1Y, Bc)), f2_mul(W2Y, D));
        ull ss2 = f2_add(f2_add(f2_mul(gx2, gx2), f2_mul(gy2, gy2)), EPS);

        float gxa, gxb, gya, gyb, ma, mb;
        unpackf2(gx2, gxa, gxb);
        unpackf2(gy2, gya, gyb);
        unpackf2(ss2, ma, mb);

        #pragma unroll
        for (int j = 0; j < 2; ++j) {
            float gxv = j ? gxb : gxa;
            float gyv = j ? gyb : gya;
            float sv  = j ? mb  : ma;
            // mag = sqrt(s)*gk  via s*rsqrt(s): continuous-effect approx (~2ulp)
            float m = __fmul_rn(__fmul_rn(sv, rsq_approx(sv)), gkr[i + j]);
            if (m > 0.001f) {
                float o = atan2f(gyv, gxv);                 // bit-exact path
                if (o < 0.0f) o = __fadd_rn(o, TWO_PI_F);   // jnp.mod(ori, 2pi)
                float ob  = __fdiv_rn(__fmul_rn(36.0f, o), TWO_PI_F);
                float bf  = floorf(ob);
                float wo1 = __fsub_rn(ob, bf);
                int   b   = (int)bf;
                if (b > NBINS - 1) b -= NBINS;
                float w = __fmul_rn(__fsub_rn(1.0f, wo1), m);
                hcol[b * HSTRIDE] = __fadd_rn(hcol[b * HSTRIDE], w);  // bank = t
            }
        }
    }

    __syncthreads();

    // ---- stage 1: unit = (bin, 32-col quarter); bin = lane (conflict-free LDS.128) ----
    {
        const int lane = t & 31;
        const int q    = t >> 5;
        {
            const ulonglong2* p = (const ulonglong2*)(hist + lane * HSTRIDE + q * 32);
            ulonglong2 e = p[0];
            ull a0 = e.x, a1 = e.y;
            #pragma unroll
            for (int j = 1; j < 8; ++j) {
                e = p[j];
                a0 = f2_add(a0, e.x);
                a1 = f2_add(a1, e.y);
            }
            a0 = f2_add(a0, a1);
            float fa, fb; unpackf2(a0, fa, fb);
            part[q * 36 + lane] = fa + fb;
        }
        if (lane < 4) {   // bins 32..35
            const int b = 32 + lane;
            const ulonglong2* p = (const ulonglong2*)(hist + b * HSTRIDE + q * 32);
            ulonglong2 e = p[0];
            ull a0 = e.x, a1 = e.y;
            #pragma unroll
            for (int j = 1; j < 8; ++j) {
                e = p[j];
                a0 = f2_add(a0, e.x);
                a1 = f2_add(a1, e.y);
            }
            a0 = f2_add(a0, a1);
            float fa, fb; unpackf2(a0, fa, fb);
            part[q * 36 + b] = fa + fb;
        }
    }
    __syncthreads();

    if (t < NBINS) {
        float v = part[t] + part[36 + t] + part[72 + t] + part[108 + t];
        binsum[t] = v * 0.0009765625f;   // /1024 exact
    }
    __syncthreads();

    // ---- smoothing + first-index argmax (warp 0) — unchanged from passing version ----
    if (t < 32) {
        const int lane = t;
        const float m0 = smw[0], m1 = smw[1], m2 = smw[2];
        float hm = (lane > 0) ? binsum[lane - 1] : 0.0f;
        float hc = binsum[lane];
        float hp = binsum[lane + 1];
        float v1 = __fadd_rn(__fadd_rn(__fmul_rn(m0, hm), __fmul_rn(m1, hc)),
                             __fmul_rn(m2, hp));
        int i1 = lane;
        if (lane < 4) {
            int b2 = 32 + lane;
            float hm2 = binsum[b2 - 1];
            float hc2 = binsum[b2];
            float hp2 = (b2 < NBINS - 1) ? binsum[b2 + 1] : 0.0f;
            float v2 = __fadd_rn(__fadd_rn(__fmul_rn(m0, hm2), __fmul_rn(m1, hc2)),
                                 __fmul_rn(m2, hp2));
            if (v2 > v1) { v1 = v2; i1 = b2; }
        }
        #pragma unroll
        for (int off = 16; off > 0; off >>= 1) {
            float ov = __shfl_xor_sync(0xffffffffu, v1, off);
            int   oi = __shfl_xor_sync(0xffffffffu, i1, off);
            if (ov > v1 || (ov == v1 && oi < i1)) { v1 = ov; i1 = oi; }
        }
        if (lane == 0) {
            float fi = (float)i1;
            float tt = __fdiv_rn(__fmul_rn(TWO_PI_F, fi), 36.0f);
            out[blockIdx.x] = -__fsub_rn(tt, PI_F);
        }
    }
}

extern "C" void kernel_launch(void* const* d_in, const int* in_sizes, int n_in,
                              void* d_out, int out_size)
{
    const float* x   = (const float*)d_in[0];
    const float* gxw = (const float*)d_in[1];
    const float* gyw = (const float*)d_in[2];
    const float* smw = (const float*)d_in[3];
    const float* gk  = (const float*)d_in[4];
    float* out = (float*)d_out;

    int B = in_sizes[0] / (PS * PS);
    OrientationFinder_83193516523885_kernel<<<B, BLK>>>(x, gxw, gyw, smw, gk, out);
}